// round 9
// baseline (speedup 1.0000x reference)
#include <cuda_runtime.h>
#include <cuda_fp16.h>
#include <mma.h>
#include <math.h>

using namespace nvcuda;

constexpr int Bq   = 4;
constexpr int Nq   = 64;
constexpr int Fq   = 64;
constexpr int FINq = 32;
constexpr int EDIMq= 32;
constexpr int FFq  = Fq * Fq;          // 4096
constexpr int ROWS = Bq * Nq;          // 256 target rows (b,n)

constexpr int NSTAGE = 4;              // cp.async pipeline stages
constexpr int CHUNK_BYTES = 16384;     // 2 edges * 8KB

__device__ float  g_H[ROWS * Fq];
__device__ float  g_H2[ROWS * Fq];
__device__ int    g_cnt[ROWS];
__device__ int    g_midx[ROWS * Nq];
// Interleaved layout: per active slot, 2048 half2; entry [c] (c = ii*64+j, ii<32)
// holds ( A[ii][j], A[ii+32][j] ). Inactive slots stay zero (never written).
__device__ __align__(16) __half2 g_Amat[(size_t)ROWS * Nq * (FFq / 2)];

__device__ int          g_bar_count = 0;
__device__ volatile int g_bar_gen   = 0;

__device__ __forceinline__ float sigm(float x) { return 1.0f / (1.0f + expf(-x)); }
__device__ __forceinline__ __half2 h2(unsigned int u) {
    return *reinterpret_cast<__half2*>(&u);
}
__device__ __forceinline__ void cp_async16(void* smem_ptr, const void* gptr) {
    unsigned sa = (unsigned)__cvta_generic_to_shared(smem_ptr);
    asm volatile("cp.async.cg.shared.global [%0], [%1], 16;" :: "r"(sa), "l"(gptr));
}
__device__ __forceinline__ void cp_commit() {
    asm volatile("cp.async.commit_group;");
}
template<int N> __device__ __forceinline__ void cp_wait() {
    asm volatile("cp.async.wait_group %0;" :: "n"(N));
}

__device__ __forceinline__ void grid_barrier() {
    __threadfence();
    __syncthreads();
    if (threadIdx.x == 0) {
        int gen = g_bar_gen;
        if (atomicAdd(&g_bar_count, 1) == ROWS - 1) {
            g_bar_count = 0;
            __threadfence();
            g_bar_gen = gen + 1;
        } else {
            while (g_bar_gen == gen) { }
        }
    }
    __syncthreads();
}

// ---------------------------------------------------------------------------
// Kernel 1: H0 = relu(X@W_embed + b) + parallel ballot mask compaction
// ---------------------------------------------------------------------------
__global__ __launch_bounds__(64) void k_embed(
    const float* __restrict__ X, const float* __restrict__ A,
    const float* __restrict__ W_embed, const float* __restrict__ b_embed,
    float* __restrict__ Hout)
{
    int row = blockIdx.x;
    int t = threadIdx.x;
    __shared__ float xs[FINq];
    if (t < FINq) xs[t] = X[row * FINq + t];
    __syncthreads();

    float acc = b_embed[t];
#pragma unroll
    for (int k = 0; k < FINq; k++) acc += xs[k] * W_embed[k * Fq + t];
    Hout[row * Fq + t] = fmaxf(acc, 0.0f);

    if (t < 32) {
        const float* Arow = A + (size_t)row * Nq;
        unsigned a0 = (Arow[t] > 0.5f) ? 1u : 0u;
        unsigned a1 = (Arow[32 + t] > 0.5f) ? 1u : 0u;
        unsigned m0 = __ballot_sync(0xffffffffu, a0);
        unsigned m1 = __ballot_sync(0xffffffffu, a1);
        unsigned lanemask = (t == 0) ? 0u : (0xffffffffu >> (32 - t));
        int n0 = __popc(m0);
        if (a0) g_midx[row * Nq + __popc(m0 & lanemask)] = t;
        if (a1) g_midx[row * Nq + n0 + __popc(m1 & lanemask)] = 32 + t;
        if (t == 0) g_cnt[row] = n0 + __popc(m1);
    }
}

// ---------------------------------------------------------------------------
// Kernel 2: edge MLP via tensor cores (wmma, fp16 in / fp32 acc).
// Block (rp, cy): 2 target rows' active slots x logical columns
// {c0..c0+127} U {c0+2048..c0+2175}  (the pair needed for interleaved output).
// A = E[active slots][32] fp16, B = W_edge[32][256 sel cols] fp16.
// grid = (128, 16), 128 threads (4 warps).
// ---------------------------------------------------------------------------
__global__ __launch_bounds__(128) void k_edge(
    const float* __restrict__ E, const float* __restrict__ W_edge,
    const float* __restrict__ b_edge)
{
    int rp = blockIdx.x;
    int c0 = blockIdx.y * 128;
    int t  = threadIdx.x;
    int w  = t >> 5;

    __shared__ __half Bsm[32][256];    // 16KB
    __shared__ __half Asm[16][32];     // 1KB
    __shared__ float  Csm[16][256];    // 16KB
    __shared__ int    s_slot[2 * Nq];
    __shared__ int    s_ne;

    if (t == 0) {
        int ne = 0;
        for (int r = 0; r < 2; r++) {
            int row = rp * 2 + r;
            int cnt = g_cnt[row];
            for (int k = 0; k < cnt; k++) s_slot[ne++] = row * Nq + k;
        }
        s_ne = ne;
    }

    // build B tile (cols c0..c0+127, then c0+2048..c0+2175)
    for (int idx = t; idx < 32 * 256; idx += 128) {
        int k = idx >> 8, n = idx & 255;
        int col = (n < 128) ? (c0 + n) : (c0 + (n - 128) + 2048);
        Bsm[k][n] = __float2half(W_edge[(size_t)k * FFq + col]);
    }
    __syncthreads();
    int ne = s_ne;

    float blo = b_edge[c0 + t];
    float bhi = b_edge[c0 + t + 2048];

    for (int mt = 0; mt * 16 < ne; mt++) {
        // build A tile (zero-pad past ne)
        for (int idx = t; idx < 16 * 32; idx += 128) {
            int m = idx >> 5, e = idx & 31;
            int mm = mt * 16 + m;
            float v = 0.0f;
            if (mm < ne) {
                int slot = s_slot[mm];
                int row  = slot >> 6;
                int mIdx = g_midx[slot];
                v = E[((size_t)row * Nq + mIdx) * EDIMq + e];
            }
            Asm[m][e] = __float2half(v);
        }
        __syncthreads();

        wmma::fragment<wmma::matrix_a, 16, 16, 16, __half, wmma::row_major> fa0, fa1;
        wmma::load_matrix_sync(fa0, &Asm[0][0], 32);
        wmma::load_matrix_sync(fa1, &Asm[0][16], 32);
        for (int nt = w; nt < 16; nt += 4) {
            wmma::fragment<wmma::matrix_b, 16, 16, 16, __half, wmma::row_major> fb;
            wmma::fragment<wmma::accumulator, 16, 16, 16, float> fc;
            wmma::fill_fragment(fc, 0.0f);
            wmma::load_matrix_sync(fb, &Bsm[0][nt * 16], 256);
            wmma::mma_sync(fc, fa0, fb, fc);
            wmma::load_matrix_sync(fb, &Bsm[16][nt * 16], 256);
            wmma::mma_sync(fc, fa1, fb, fc);
            wmma::store_matrix_sync(&Csm[0][nt * 16], fc, 256, wmma::mem_row_major);
        }
        __syncthreads();

        // repack: thread t owns column pair (c0+t, c0+t+2048)
        int nv = min(16, ne - mt * 16);
        for (int m = 0; m < nv; m++) {
            int slot = s_slot[mt * 16 + m];
            float lo = fmaxf(Csm[m][t]       + blo, 0.0f);
            float hi = fmaxf(Csm[m][128 + t] + bhi, 0.0f);
            g_Amat[(size_t)slot * (FFq / 2) + c0 + t] = __floats2half2_rn(lo, hi);
        }
        __syncthreads();
    }
}

// ---------------------------------------------------------------------------
// Kernel 3: ALL 3 rounds in one persistent launch. 256 blocks x 512 threads,
// 2 blocks/SM (296 slots >= 256 -> all co-resident, grid barrier safe).
// Per round: cp.async 4-stage pipeline over 2-edge 16KB chunks + fused GRU.
// Rounds 2-3 benefit from warm L2 (Amat) and warm L1 (gk/grk).
// ---------------------------------------------------------------------------
constexpr int SMEM_STAGE = NSTAGE * CHUNK_BYTES;                  // 65536
constexpr int SMEM_HS    = (Nq + 1) * Fq * 4;                     // 16640
constexpr int SMEM_FLT   = (64 * 3 + 128 + 192 * 3) * 4;          // 3584
constexpr int SMEM_TOTAL = SMEM_STAGE + SMEM_HS + SMEM_FLT;       // 85760

__global__ __launch_bounds__(512) void k_rounds(
    const float* __restrict__ gk, const float* __restrict__ grk,
    const float* __restrict__ gb, const float* __restrict__ grb,
    float* __restrict__ out)
{
    extern __shared__ __align__(16) char smem[];
    char* stage = smem;
    __half2 (*hs2)[Fq] = reinterpret_cast<__half2(*)[Fq]>(smem + SMEM_STAGE);
    float* fl   = reinterpret_cast<float*>(smem + SMEM_STAGE + SMEM_HS);
    float* xold = fl;            // 64
    float* aggv = fl + 64;       // 64
    float* h1   = fl + 128;      // 64
    float* aggp = fl + 192;      // 2*64
    float* xg1  = fl + 320;      // 192
    float* xg2  = fl + 512;      // 192
    float* hg2  = fl + 704;      // 192

    int row = blockIdx.x;
    int b = row >> 6;
    int t = threadIdx.x;
    int ee = t >> 8;              // edge within chunk
    int tt = t & 255;
    int ii = tt >> 3, jq = tt & 7;

    int cnt = g_cnt[row];
    int nchunk = (cnt + 1) >> 1;

    const char* Asrc = reinterpret_cast<const char*>(g_Amat)
                     + (size_t)row * Nq * 8192;

    for (int r = 0; r < 3; r++) {
        const float* Hin = (r == 0) ? g_H : ((r == 1) ? g_H2 : g_H);
        float* Hout = (r == 0) ? g_H2 : ((r == 1) ? g_H : out);

        auto issue = [&](int c) {
            const char* src = Asrc + (size_t)c * CHUNK_BYTES;
            char* dst = stage + (c & (NSTAGE - 1)) * CHUNK_BYTES;
            cp_async16(dst + t * 16, src + t * 16);
            cp_async16(dst + t * 16 + 8192, src + t * 16 + 8192);
        };

        // prologue
#pragma unroll
        for (int s = 0; s < NSTAGE - 1; s++) {
            if (s < nchunk) issue(s);
            cp_commit();
        }

        // stage sources (L2 reads: fresh across rounds)
        for (int idx = t; idx < cnt * Fq; idx += 512) {
            int e = idx >> 6, j = idx & 63;
            int m = g_midx[row * Nq + e];
            float v = __ldcg(&Hin[((size_t)b * Nq + m) * Fq + j]);
            hs2[e][j] = __float2half2_rn(v);
        }
        if (t < Fq) hs2[cnt][t] = __float2half2_rn(0.0f);
        if (t >= 64 && t < 128) xold[t - 64] = __ldcg(&Hin[(size_t)row * Fq + (t - 64)]);

        float flo = 0.0f, fhi = 0.0f;

        for (int c = 0; c < nchunk; c++) {
            cp_wait<NSTAGE - 2>();
            __syncthreads();

            const uint4* ap = reinterpret_cast<const uint4*>(
                stage + (c & (NSTAGE - 1)) * CHUNK_BYTES) + ee * 512 + ii * 16 + jq * 2;
            uint4 a0 = ap[0];
            uint4 a1 = ap[1];
            int e = 2 * c + ee;   // pad edge: A zeros, hs2 zeros
            const uint4* hp = reinterpret_cast<const uint4*>(&hs2[e][jq * 8]);
            uint4 hA = hp[0];
            uint4 hB = hp[1];
            __half2 cA = __hmul2(h2(a0.x), h2(hA.x));
            cA = __hfma2(h2(a0.y), h2(hA.y), cA);
            cA = __hfma2(h2(a0.z), h2(hA.z), cA);
            cA = __hfma2(h2(a0.w), h2(hA.w), cA);
            __half2 cB = __hmul2(h2(a1.x), h2(hB.x));
            cB = __hfma2(h2(a1.y), h2(hB.y), cB);
            cB = __hfma2(h2(a1.z), h2(hB.z), cB);
            cB = __hfma2(h2(a1.w), h2(hB.w), cB);
            float2 f = __half22float2(__hadd2(cA, cB));
            flo += f.x;
            fhi += f.y;

            int nx = c + NSTAGE - 1;
            if (nx < nchunk) issue(nx);
            cp_commit();
        }
        cp_wait<0>();

        flo += __shfl_xor_sync(0xffffffffu, flo, 1);
        flo += __shfl_xor_sync(0xffffffffu, flo, 2);
        flo += __shfl_xor_sync(0xffffffffu, flo, 4);
        fhi += __shfl_xor_sync(0xffffffffu, fhi, 1);
        fhi += __shfl_xor_sync(0xffffffffu, fhi, 2);
        fhi += __shfl_xor_sync(0xffffffffu, fhi, 4);
        if (jq == 0) {
            aggp[ee * 64 + ii] = flo;
            aggp[ee * 64 + ii + 32] = fhi;
        }
        __syncthreads();
        if (t < Fq) aggv[t] = aggp[t] + aggp[64 + t];
        __syncthreads();

        // ---- GRU: one pass over gk computes both steps' input gates ----
        if (t < 192) {
            float a1 = gb[t], a2 = gb[t];
#pragma unroll 8
            for (int j = 0; j < Fq; j++) {
                float wv = gk[j * 192 + t];
                a1 += xold[j] * wv;
                a2 += aggv[j] * wv;
            }
            xg1[t] = a1;
            xg2[t] = a2;
        }
        __syncthreads();
        if (t < Fq) {
            float z = sigm(xg1[t] + grb[t]);
            float rr = sigm(xg1[Fq + t] + grb[Fq + t]);
            float cand = tanhf(xg1[2 * Fq + t] + rr * grb[2 * Fq + t]);
            h1[t] = (1.0f - z) * cand;
        }
        __syncthreads();
        if (t < 192) {
            float hh = grb[t];
#pragma unroll 8
            for (int j = 0; j < Fq; j++) hh += h1[j] * grk[j * 192 + t];
            hg2[t] = hh;
        }
        __syncthreads();
        if (t < Fq) {
            float z = sigm(xg2[t] + hg2[t]);
            float rr = sigm(xg2[Fq + t] + hg2[Fq + t]);
            float cand = tanhf(xg2[2 * Fq + t] + rr * hg2[2 * Fq + t]);
            Hout[(size_t)row * Fq + t] = z * h1[t] + (1.0f - z) * cand;
        }

        if (r < 2) grid_barrier();
    }
}

// ---------------------------------------------------------------------------
extern "C" void kernel_launch(void* const* d_in, const int* in_sizes, int n_in,
                              void* d_out, int out_size)
{
    const float* X       = (const float*)d_in[0];
    const float* A       = (const float*)d_in[1];
    const float* E       = (const float*)d_in[2];
    const float* W_embed = (const float*)d_in[3];
    const float* b_embed = (const float*)d_in[4];
    const float* W_edge  = (const float*)d_in[5];
    const float* b_edge  = (const float*)d_in[6];
    const float* gk      = (const float*)d_in[7];
    const float* grk     = (const float*)d_in[8];
    const float* gb      = (const float*)d_in[9];
    const float* grb     = (const float*)d_in[10];
    float* out = (float*)d_out;

    float* hbuf = nullptr;
    cudaGetSymbolAddress((void**)&hbuf, g_H);

    static bool attr_set = false;
    if (!attr_set) {
        cudaFuncSetAttribute(k_rounds, cudaFuncAttributeMaxDynamicSharedMemorySize,
                             SMEM_TOTAL);
        attr_set = true;
    }

    k_embed<<<ROWS, 64>>>(X, A, W_embed, b_embed, hbuf);
    k_edge<<<dim3(ROWS / 2, 16), 128>>>(E, W_edge, b_edge);
    k_rounds<<<ROWS, 512, SMEM_TOTAL>>>(gk, grk, gb, grb, out);
}